// round 2
// baseline (speedup 1.0000x reference)
#include <cuda_runtime.h>

#define NR 32
#define NA 16
// 4-way rule split: lane rg = tid&3 handles rules rg*8 .. rg*8+7
#define RG 4
#define RPT 8          // rules per thread
#define TPB 128        // threads per block
#define SPB 64         // samples per block (TPB/RG pairs * 2)

static __device__ __forceinline__ unsigned long long pack2(float lo, float hi) {
    unsigned long long r;
    asm("mov.b64 %0, {%1, %2};" : "=l"(r) : "f"(lo), "f"(hi));
    return r;
}
static __device__ __forceinline__ void unpack2(unsigned long long v, float& lo, float& hi) {
    asm("mov.b64 {%0, %1}, %2;" : "=f"(lo), "=f"(hi) : "l"(v));
}
static __device__ __forceinline__ unsigned long long fma2(
    unsigned long long a, unsigned long long b, unsigned long long c) {
    unsigned long long d;
    asm("fma.rn.f32x2 %0, %1, %2, %3;" : "=l"(d) : "l"(a), "l"(b), "l"(c));
    return d;
}
static __device__ __forceinline__ unsigned long long add2(
    unsigned long long a, unsigned long long b) {
    unsigned long long d;
    asm("add.rn.f32x2 %0, %1, %2;" : "=l"(d) : "l"(a), "l"(b));
    return d;
}
static __device__ __forceinline__ float ex2(float x) {
    float y;
    asm("ex2.approx.f32 %0, %1;" : "=f"(y) : "f"(x));
    return y;
}

__global__ __launch_bounds__(TPB)
void tsk_kernel(const float* __restrict__ input,
                const float* __restrict__ frbw,
                const float* __restrict__ C,
                float* __restrict__ out, int B)
{
    // Per-rule-group coefficient arrays, stride 129 (=8*16+1) entries to skew
    // banks: rg offsets 0 / 129*16B=2064 / 4128 / 6192 bytes -> distinct banks.
    __shared__ ulonglong2          s_pq[RG * (RPT * NA + 1)];  // (p,p,q,q) dup pairs
    __shared__ unsigned long long  s_cc[RG * (RPT * NA + 1)];  // (c,c)
    __shared__ unsigned long long  s_rc[NR];                   // rule const (dup)
    __shared__ unsigned long long  s_c0[NR];                   // C[r][0]   (dup)
    __shared__ float               s_ct[NR * NA];              // scratch

    const float L2E = 1.4426950408889634f;
    const int tid = threadIdx.x;

    // ---- coefficient precompute (runs once per block, tiny) ----
    for (int i = tid; i < NR * NA; i += TPB) {
        // Faithful to reference: idx = r*A + k; (sigma, center) = FRB_W[idx], FRB_W[idx+1]
        float sig = frbw[i];
        float cen = frbw[i + 1];
        float is2 = 1.0f / (sig * sig);
        float p = -0.5f * is2 * L2E;
        float q = is2 * cen * L2E;
        int r = i >> 4, k = i & 15;
        int rg = r >> 3, j = r & 7;
        int o = rg * (RPT * NA + 1) + j * NA + k;
        s_pq[o] = make_ulonglong2(pack2(p, p), pack2(q, q));
        float cc = C[r * (NA + 1) + k + 1];
        s_cc[o] = pack2(cc, cc);
        s_ct[i] = p * cen * cen;
    }
    __syncthreads();
    if (tid < NR) {
        float acc = 0.0f;
        #pragma unroll
        for (int k = 0; k < NA; k++) acc += s_ct[tid * NA + k];
        s_rc[tid] = pack2(acc, acc);
        float c0 = C[tid * (NA + 1)];
        s_c0[tid] = pack2(c0, c0);
    }
    __syncthreads();

    // ---- thread mapping: rg = tid&3 (rule group), sp = tid>>2 (sample pair) ----
    const int rg = tid & 3;
    const int sp = tid >> 2;
    int s0 = blockIdx.x * SPB + sp * 2;
    int s1 = s0 + 1;
    bool v = s0 < B;
    int l0 = v ? s0 : 0;
    int l1 = (s1 < B) ? s1 : l0;

    // load the two 16-float rows, pack lane-pairs
    const float4* in4 = (const float4*)input;
    unsigned long long X[NA];
    #pragma unroll
    for (int j = 0; j < 4; j++) {
        float4 a = in4[l0 * 4 + j];
        float4 b = in4[l1 * 4 + j];
        X[j * 4 + 0] = pack2(a.x, b.x);
        X[j * 4 + 1] = pack2(a.y, b.y);
        X[j * 4 + 2] = pack2(a.z, b.z);
        X[j * 4 + 3] = pack2(a.w, b.w);
    }

    const ulonglong2* pq = s_pq + rg * (RPT * NA + 1);
    const unsigned long long* cc = s_cc + rg * (RPT * NA + 1);
    const int rbase = rg * RPT;

    unsigned long long num = 0ull;
    unsigned long long den = 0ull;

    #pragma unroll 1          // keep body ~80 instrs, resident in L0 I$
    for (int j = 0; j < RPT; j++) {
        unsigned long long e  = s_rc[rbase + j];
        unsigned long long ch = s_c0[rbase + j];
        #pragma unroll
        for (int k = 0; k < NA; k++) {
            ulonglong2 w = pq[j * NA + k];         // one LDS.128: (p,p,q,q)
            unsigned long long t = fma2(w.x, X[k], w.y);
            e  = fma2(t, X[k], e);
            ch = fma2(cc[j * NA + k], X[k], ch);   // one LDS.64
        }
        float e0, e1;
        unpack2(e, e0, e1);
        unsigned long long u = pack2(ex2(e0), ex2(e1));
        num = fma2(u, ch, num);
        den = add2(den, u);
    }

    // ---- reduce across the 4 rule-group lanes (adjacent lanes) ----
    #pragma unroll
    for (int m = 1; m < RG; m <<= 1) {
        num = add2(num, __shfl_xor_sync(0xFFFFFFFFu, num, m));
        den = add2(den, __shfl_xor_sync(0xFFFFFFFFu, den, m));
    }

    if (rg == 0 && v) {
        float n0, n1, d0, d1;
        unpack2(num, n0, n1);
        unpack2(den, d0, d1);
        float2 o2 = make_float2(__fdividef(n0, d0), __fdividef(n1, d1));
        *(float2*)(out + s0) = o2;   // s0 even -> 8B aligned
    }
}

extern "C" void kernel_launch(void* const* d_in, const int* in_sizes, int n_in,
                              void* d_out, int out_size)
{
    const float* input = (const float*)d_in[0];   // [B, 16] fp32
    const float* frbw  = (const float*)d_in[1];   // [1024]  fp32
    const float* Cm    = (const float*)d_in[2];   // [32,17] fp32
    float* out = (float*)d_out;                   // [B]     fp32

    int B = in_sizes[0] / NA;
    int blocks = (B + SPB - 1) / SPB;             // 1024 blocks for B=65536
    tsk_kernel<<<blocks, TPB>>>(input, frbw, Cm, out, B);
}

// round 3
// speedup vs baseline: 1.3631x; 1.3631x over previous
#include <cuda_runtime.h>

#define NR 32
#define NA 16
#define TPB 128        // 2 halves of 64 threads
#define SPT 4          // samples per thread (2 f32x2 pairs)
#define SPB 256        // samples per block = 64 threads * 4

static __device__ __forceinline__ unsigned long long pack2(float lo, float hi) {
    unsigned long long r;
    asm("mov.b64 %0, {%1, %2};" : "=l"(r) : "f"(lo), "f"(hi));
    return r;
}
static __device__ __forceinline__ void unpack2(unsigned long long v, float& lo, float& hi) {
    asm("mov.b64 {%0, %1}, %2;" : "=f"(lo), "=f"(hi) : "l"(v));
}
static __device__ __forceinline__ unsigned long long fma2(
    unsigned long long a, unsigned long long b, unsigned long long c) {
    unsigned long long d;
    asm("fma.rn.f32x2 %0, %1, %2, %3;" : "=l"(d) : "l"(a), "l"(b), "l"(c));
    return d;
}
static __device__ __forceinline__ unsigned long long add2(
    unsigned long long a, unsigned long long b) {
    unsigned long long d;
    asm("add.rn.f32x2 %0, %1, %2;" : "=l"(d) : "l"(a), "l"(b));
    return d;
}
static __device__ __forceinline__ float ex2(float x) {
    float y;
    asm("ex2.approx.f32 %0, %1;" : "=f"(y) : "f"(x));
    return y;
}

__global__ __launch_bounds__(TPB)
void tsk_kernel(const float* __restrict__ input,
                const float* __restrict__ frbw,
                const float* __restrict__ C,
                float* __restrict__ out, int B)
{
    // Coefficients per rule-half; within a warp ALL lanes read the SAME
    // address -> perfect smem broadcast (1 wavefront per LDS).
    __shared__ ulonglong2         s_pq[2][NA * NA];  // (p,p,q,q) per (rule,k)
    __shared__ unsigned long long s_cc[2][NA * NA];  // (c,c)
    __shared__ unsigned long long s_rc[NR];          // rule const (dup pair)
    __shared__ unsigned long long s_c0[NR];          // C[r][0]    (dup pair)
    __shared__ float              s_ct[NR * NA];     // scratch
    __shared__ ulonglong2         s_redA[64];        // (num,den) pair A, half 1
    __shared__ ulonglong2         s_redB[64];        // (num,den) pair B, half 1

    const float L2E = 1.4426950408889634f;
    const int tid = threadIdx.x;

    // ---- coefficient precompute (once per block, 4 iters/thread) ----
    for (int i = tid; i < NR * NA; i += TPB) {
        // Faithful to reference: idx=r*A+k; (sigma,center)=FRB_W[idx],FRB_W[idx+1]
        float sig = frbw[i];
        float cen = frbw[i + 1];
        float is2 = 1.0f / (sig * sig);
        float p = -0.5f * is2 * L2E;
        float q = is2 * cen * L2E;
        int r = i >> 4, k = i & 15;
        int h = r >> 4, j = r & 15;
        s_pq[h][j * NA + k] = make_ulonglong2(pack2(p, p), pack2(q, q));
        float cc = C[r * (NA + 1) + k + 1];
        s_cc[h][j * NA + k] = pack2(cc, cc);
        s_ct[i] = p * cen * cen;
    }
    __syncthreads();
    if (tid < NR) {
        float acc = 0.0f;
        #pragma unroll
        for (int k = 0; k < NA; k++) acc += s_ct[tid * NA + k];
        s_rc[tid] = pack2(acc, acc);
        s_c0[tid] = pack2(C[tid * (NA + 1)], C[tid * (NA + 1)]);
    }
    __syncthreads();

    // ---- mapping: half h (rules h*16..h*16+15), t = sample slot ----
    const int h = tid >> 6;        // 0 or 1 (warps 0,1 vs 2,3)
    const int t = tid & 63;
    const int s = blockIdx.x * SPB + t * SPT;   // first of 4 samples

    // clamp row indices for the (rare) tail
    int r0 = s,     r1 = s + 1,   r2 = s + 2,   r3 = s + 3;
    if (r0 >= B) r0 = B - 1;
    if (r1 >= B) r1 = B - 1;
    if (r2 >= B) r2 = B - 1;
    if (r3 >= B) r3 = B - 1;

    const float4* in4 = (const float4*)input;
    unsigned long long XA[NA], XB[NA];
    #pragma unroll
    for (int j = 0; j < 4; j++) {
        float4 a = in4[r0 * 4 + j];
        float4 b = in4[r1 * 4 + j];
        float4 c = in4[r2 * 4 + j];
        float4 d = in4[r3 * 4 + j];
        XA[j * 4 + 0] = pack2(a.x, b.x);  XB[j * 4 + 0] = pack2(c.x, d.x);
        XA[j * 4 + 1] = pack2(a.y, b.y);  XB[j * 4 + 1] = pack2(c.y, d.y);
        XA[j * 4 + 2] = pack2(a.z, b.z);  XB[j * 4 + 2] = pack2(c.z, d.z);
        XA[j * 4 + 3] = pack2(a.w, b.w);  XB[j * 4 + 3] = pack2(c.w, d.w);
    }

    const ulonglong2*         pq = s_pq[h];
    const unsigned long long* cc = s_cc[h];
    const int rbase = h * NA;

    unsigned long long numA = 0ull, denA = 0ull;
    unsigned long long numB = 0ull, denB = 0ull;

    #pragma unroll 2
    for (int j = 0; j < NA; j++) {       // 16 rules in this half
        unsigned long long eA  = s_rc[rbase + j];
        unsigned long long eB  = eA;
        unsigned long long chA = s_c0[rbase + j];
        unsigned long long chB = chA;
        #pragma unroll
        for (int k = 0; k < NA; k++) {
            ulonglong2 w = pq[j * NA + k];            // 1 LDS.128 broadcast
            unsigned long long ccw = cc[j * NA + k];  // 1 LDS.64 broadcast
            unsigned long long tA = fma2(w.x, XA[k], w.y);
            unsigned long long tB = fma2(w.x, XB[k], w.y);
            eA  = fma2(tA, XA[k], eA);
            eB  = fma2(tB, XB[k], eB);
            chA = fma2(ccw, XA[k], chA);
            chB = fma2(ccw, XB[k], chB);
        }
        float a0, a1, b0, b1;
        unpack2(eA, a0, a1);
        unpack2(eB, b0, b1);
        unsigned long long uA = pack2(ex2(a0), ex2(a1));
        unsigned long long uB = pack2(ex2(b0), ex2(b1));
        numA = fma2(uA, chA, numA);  denA = add2(denA, uA);
        numB = fma2(uB, chB, numB);  denB = add2(denB, uB);
    }

    // ---- combine the two rule halves via smem ----
    if (h == 1) {
        s_redA[t] = make_ulonglong2(numA, denA);
        s_redB[t] = make_ulonglong2(numB, denB);
    }
    __syncthreads();
    if (h == 0 && s < B) {
        ulonglong2 pA = s_redA[t];
        ulonglong2 pB = s_redB[t];
        numA = add2(numA, pA.x);  denA = add2(denA, pA.y);
        numB = add2(numB, pB.x);  denB = add2(denB, pB.y);
        float n0, n1, n2, n3, d0, d1, d2, d3;
        unpack2(numA, n0, n1);  unpack2(denA, d0, d1);
        unpack2(numB, n2, n3);  unpack2(denB, d2, d3);
        if (s + 3 < B) {
            float4 o = make_float4(__fdividef(n0, d0), __fdividef(n1, d1),
                                   __fdividef(n2, d2), __fdividef(n3, d3));
            *(float4*)(out + s) = o;   // s % 4 == 0 -> 16B aligned
        } else {
            float v[4] = {__fdividef(n0, d0), __fdividef(n1, d1),
                          __fdividef(n2, d2), __fdividef(n3, d3)};
            for (int i = 0; i < 4 && s + i < B; i++) out[s + i] = v[i];
        }
    }
}

extern "C" void kernel_launch(void* const* d_in, const int* in_sizes, int n_in,
                              void* d_out, int out_size)
{
    const float* input = (const float*)d_in[0];   // [B, 16] fp32
    const float* frbw  = (const float*)d_in[1];   // [1024]  fp32
    const float* Cm    = (const float*)d_in[2];   // [32,17] fp32
    float* out = (float*)d_out;                   // [B]     fp32

    int B = in_sizes[0] / NA;
    int blocks = (B + SPB - 1) / SPB;             // 256 blocks for B=65536
    tsk_kernel<<<blocks, TPB>>>(input, frbw, Cm, out, B);
}